// round 5
// baseline (speedup 1.0000x reference)
#include <cuda_runtime.h>
#include <float.h>

#define TT   3
#define HH   192
#define WW   192
#define CC   64
#define HWSZ (HH*WW)
#define NHC  24
#define NWC  24
#define Q1   (TT*NHC*NWC)   // 1728
#define NHF  48
#define NWF  48
#define QF   (TT*NHF*NWF)   // 6912
#define KK   7
#define SS   192            // candidates per query

// scratch (static __device__ arrays — allowed; no runtime allocation)
__device__ float g_v0t[TT*HWSZ*CC];
__device__ float g_v1t[TT*HWSZ*CC];
__device__ float g_sd[Q1*SS];
__device__ int   g_inds[Q1*KK*3];

__device__ __forceinline__ int refl(int i, int L) {
    i = i < 0 ? -i : i;
    return (i >= L) ? (2*(L-1) - i) : i;
}

// ---------------------------------------------------------------------------
// Transpose (T,C,H,W) -> (T,H,W,C), channels-last, for both videos.
// ---------------------------------------------------------------------------
__global__ void __launch_bounds__(256) transpose_kernel(const float* __restrict__ v0,
                                                        const float* __restrict__ v1) {
    const float* src = (blockIdx.z == 0) ? v0 : v1;
    float* dst       = (blockIdx.z == 0) ? g_v0t : g_v1t;
    const int t    = blockIdx.y;
    const int pix0 = blockIdx.x * 32;

    __shared__ float tile[CC][33];
    const int tx  = threadIdx.x & 31;
    const int grp = threadIdx.x >> 5;   // 0..7

    #pragma unroll
    for (int cc = 0; cc < CC; cc += 8) {
        int c = cc + grp;
        tile[c][tx] = src[((size_t)(t*CC + c))*HWSZ + pix0 + tx];
    }
    __syncthreads();
    #pragma unroll
    for (int i = 0; i < 8; ++i) {
        int idx = i*256 + threadIdx.x;        // 0..2047
        int pix = idx >> 6;                   // 0..31
        int ch  = idx & 63;
        dst[((size_t)t*HWSZ + pix0 + pix)*CC + ch] = tile[ch][pix];
    }
}

// ---------------------------------------------------------------------------
// Stage 1a: candidate distances with XLA-replicating fp32 arithmetic.
// grid (Q1, 3): block handles (query q, candidate-time t); 64 threads =
// candidates (dyi 0..7, dxi 0..7).
// Per candidate: acc = 0; for each of 49 patch offsets in (dr major, dc
// ascending) order: p = sequential fma chain over c = 0..63; acc = acc + p.
// This matches scan(einsum) with a sequential-K dot lowering bit-for-bit,
// which is required to reproduce the reference's fp-noise tie resolution on
// mirror-tied border candidates. DO NOT REORDER the arithmetic.
// ---------------------------------------------------------------------------
#define CSTR 68                   // padded col stride (floats): conflict-free
#define RSTR (15*CSTR)            // row stride

__global__ void __launch_bounds__(64) stage1a_kernel() {
    const int q  = blockIdx.x;
    const int t  = blockIdx.y;
    const int qt = q / (NHC*NWC);
    const int rr = q % (NHC*NWC);
    const int qh = (rr / NWC) * 8;
    const int qw = (rr % NWC) * 8;

    __shared__ float sq[49*CC];      // query patch  (12.25 KB)
    __shared__ float sv[8*RSTR];     // 8 rows x 15 cols x 64c padded (31.9 KB)

    const int tid = threadIdx.x;
    const int dyi = tid >> 3;
    const int dxi = tid & 7;

    // load query patch (reflected) as float4
    for (int i = tid; i < 49*16; i += 64) {
        int o = i >> 4, c4 = i & 15;
        int y = refl(qh + (o/7) - 3, HH);
        int x = refl(qw + (o%7) - 3, WW);
        reinterpret_cast<float4*>(sq)[i] =
            reinterpret_cast<const float4*>(g_v0t + ((size_t)qt*HWSZ + (size_t)y*WW + x)*CC)[c4];
    }

    const int clo = (qw - 7 < 0) ? 0 : (qw - 7);
    float acc = 0.f;

    for (int dri = 0; dri < 7; ++dri) {
        const int a   = qh + dri - 7;
        const int rlo = (a < 0) ? 0 : a;

        __syncthreads();   // protect previous iteration's sv reads
        // load 8 rows x 15 cols x 64 ch (abs rows rlo.., abs cols clo..)
        for (int i = tid; i < 8*15*16; i += 64) {
            int row = i / (15*16);
            int rem = i % (15*16);
            int col = rem >> 4, c4 = rem & 15;
            float4 v = reinterpret_cast<const float4*>(
                g_v1t + ((size_t)t*HWSZ + (size_t)(rlo+row)*WW + (clo+col))*CC)[c4];
            *reinterpret_cast<float4*>(sv + row*RSTR + col*CSTR + c4*4) = v;
        }
        __syncthreads();

        const int myrow = refl(qh + (dyi - 4) + (dri - 3), HH) - rlo;
        const float* vrow = sv + myrow*RSTR;

        #pragma unroll
        for (int ox = 0; ox < 7; ++ox) {
            const int x1 = refl(qw + (dxi - 4) + (ox - 3), WW) - clo;
            const float* vp = vrow + x1*CSTR;
            const float* qp = sq + (dri*7 + ox)*CC;
            float p = 0.f;
            #pragma unroll
            for (int c4 = 0; c4 < 16; ++c4) {
                float4 a4 = reinterpret_cast<const float4*>(qp)[c4];
                float4 b4 = *reinterpret_cast<const float4*>(vp + c4*4);
                p = fmaf(a4.x, b4.x, p);
                p = fmaf(a4.y, b4.y, p);
                p = fmaf(a4.z, b4.z, p);
                p = fmaf(a4.w, b4.w, p);
            }
            acc = acc + p;       // sequential 49-term scan sum
        }
    }
    g_sd[q*SS + t*64 + dyi*8 + dxi] = acc;
}

// ---------------------------------------------------------------------------
// Stage 1b: stable top-7 per query (argmax with lowest-index tie break,
// exactly lax.top_k semantics). 192 threads per query.
// ---------------------------------------------------------------------------
__global__ void __launch_bounds__(192) stage1b_kernel() {
    const int q  = blockIdx.x;
    const int rr = q % (NHC*NWC);
    const int qh = (rr / NWC) * 8;
    const int qw = (rr % NWC) * 8;

    __shared__ float sd[SS];
    __shared__ float rv[256];
    __shared__ int   ri[256];

    const int tid = threadIdx.x;
    sd[tid] = g_sd[q*SS + tid];
    __syncthreads();

    for (int k = 0; k < KK; ++k) {
        rv[tid] = sd[tid]; ri[tid] = tid;
        if (tid < 64) { rv[192 + tid] = -FLT_MAX; ri[192 + tid] = 255; }
        __syncthreads();
        #pragma unroll
        for (int s = 128; s >= 1; s >>= 1) {
            if (tid < s) {
                float v2 = rv[tid + s]; int i2 = ri[tid + s];
                if (v2 > rv[tid] || (v2 == rv[tid] && i2 < ri[tid])) {
                    rv[tid] = v2; ri[tid] = i2;
                }
            }
            __syncthreads();
        }
        if (tid == 0) {
            int sel = ri[0];
            sd[sel] = -FLT_MAX;
            int base = (q*KK + k)*3;
            g_inds[base + 0] = sel >> 6;                   // ct
            g_inds[base + 1] = qh + ((sel >> 3) & 7) - 4;  // ch (raw)
            g_inds[base + 2] = qw + (sel & 7) - 4;         // cw (raw)
        }
        __syncthreads();
    }
}

// ---------------------------------------------------------------------------
// Stage 2+3 fused: upsample indices to fine grid + refine dists.
// block = 224 threads (7 warps) per fine query; warp k handles candidate k.
// inds_f written as FLOATS (harness compares the whole d_out as float32).
// ---------------------------------------------------------------------------
__global__ void __launch_bounds__(224) stage3_kernel(float* __restrict__ out) {
    const int q  = blockIdx.x;
    const int ft = q / (NHF*NWF);
    const int rr = q % (NHF*NWF);
    const int fi = rr / NWF, fj = rr % NWF;
    const int fh = fi*4, fw = fj*4;

    __shared__ float sp[49*CC];
    __shared__ int   scand[KK*3];

    const int tid = threadIdx.x;
    for (int i = tid; i < 49*CC; i += 224) {
        int o = i >> 6, c = i & 63;
        int y = refl(fh + (o/7) - 3, HH);
        int x = refl(fw + (o%7) - 3, WW);
        sp[i] = g_v0t[((size_t)ft*HWSZ + (size_t)y*WW + x)*CC + c];
    }
    if (tid < KK) {
        int it, ih, iw;
        if (tid == 0) { it = ft; ih = fh; iw = fw; }
        else {
            int ci = min(fi >> 1, NHC - 1);
            int cj = min(fj >> 1, NWC - 1);
            int qlin = ft*NHC*NWC + ci*NWC + cj;
            int b = (qlin*KK + tid)*3;
            it = g_inds[b + 0];
            ih = refl(g_inds[b + 1] + (fh - ci*8), HH);
            iw = refl(g_inds[b + 2] + (fw - cj*8), WW);
        }
        scand[tid*3 + 0] = it;
        scand[tid*3 + 1] = ih;
        scand[tid*3 + 2] = iw;
        // inds_f (as float), laid out after dists_f
        size_t ob = (size_t)QF*KK + ((size_t)q*KK + tid)*3;
        out[ob + 0] = (float)it;
        out[ob + 1] = (float)ih;
        out[ob + 2] = (float)iw;
    }
    __syncthreads();

    const int warp = tid >> 5;
    const int lane = tid & 31;
    const int it = scand[warp*3 + 0];
    const int ih = scand[warp*3 + 1];
    const int iw = scand[warp*3 + 2];
    const float* v1b = g_v1t + (size_t)it*HWSZ*CC + 2*lane;

    float2 acc = make_float2(0.f, 0.f);
    #pragma unroll 7
    for (int o = 0; o < 49; ++o) {
        int y1 = refl(ih + o/7 - 3, HH);
        int x1 = refl(iw + o%7 - 3, WW);
        float2 wv = *reinterpret_cast<const float2*>(v1b + ((size_t)y1*WW + x1)*CC);
        float2 pv = *reinterpret_cast<const float2*>(&sp[o*CC + 2*lane]);
        acc.x = fmaf(pv.x, wv.x, acc.x);
        acc.y = fmaf(pv.y, wv.y, acc.y);
    }
    float v = acc.x + acc.y;
    #pragma unroll
    for (int s = 16; s > 0; s >>= 1)
        v += __shfl_down_sync(0xffffffffu, v, s);
    if (lane == 0)
        out[(size_t)q*KK + warp] = v;
}

// ---------------------------------------------------------------------------
extern "C" void kernel_launch(void* const* d_in, const int* in_sizes, int n_in,
                              void* d_out, int out_size) {
    const float* vid0 = (const float*)d_in[0];
    const float* vid1 = (const float*)d_in[1];
    // d_in[2] = flows, unused by the reference

    dim3 tgrid(HWSZ/32, TT, 2);
    transpose_kernel<<<tgrid, 256>>>(vid0, vid1);
    stage1a_kernel<<<dim3(Q1, TT), 64>>>();
    stage1b_kernel<<<Q1, 192>>>();
    stage3_kernel<<<QF, 224>>>((float*)d_out);
}